// round 15
// baseline (speedup 1.0000x reference)
#include <cuda_runtime.h>
#include <cuda_fp16.h>
#include <math.h>
#include <cstdint>

#define NQ 32400
#define NT 32512          // 254*128 padded
#define CDIM 512
#define NCLS 19
#define KNN 9
#define SHORTL 16
#define LANEL 12
#define HWIN (270*480)
#define FULLHW (1080*1920)
#define NCHUNK 8          // K chunks of 64 fp16 (128B rows)
#define NTILE 254         // candidate tiles of 128
#define TOT (NTILE*NCHUNK)
#define NSTAGE 3
#define STAGEB 16384      // B only

// ---------------- device scratch ----------------
__device__ float g_feats[(size_t)NT * CDIM];
__device__ float g_fs[NT];
__device__ int   g_cls[NQ];
__device__ float g_psq[NCLS];
__device__ __align__(1024) __half g_featsh[(size_t)NCHUNK * NT * 64];
__device__ int g_short[(size_t)NT * SHORTL];

// ---------------- helpers ----------------
__device__ __forceinline__ uint32_t smem_u32(const void* p) {
    uint32_t a;
    asm("{ .reg .u64 t; cvta.to.shared.u64 t, %1; cvt.u32.u64 %0, t; }" : "=r"(a) : "l"(p));
    return a;
}
__device__ __forceinline__ void mbar_init(uint32_t a, uint32_t n) {
    asm volatile("mbarrier.init.shared.b64 [%0], %1;" :: "r"(a), "r"(n) : "memory");
}
__device__ __forceinline__ void mbar_expect(uint32_t a, uint32_t bytes) {
    asm volatile("mbarrier.arrive.expect_tx.shared.b64 _, [%0], %1;" :: "r"(a), "r"(bytes) : "memory");
}
__device__ __forceinline__ void mbar_arrive(uint32_t a) {
    asm volatile("mbarrier.arrive.shared.b64 _, [%0];" :: "r"(a) : "memory");
}
__device__ __forceinline__ void mbar_wait_acq(uint32_t a, uint32_t ph) {
    asm volatile(
        "{\n\t.reg .pred P;\n"
        "W%=:\n\t"
        "mbarrier.try_wait.parity.acquire.cta.shared::cta.b64 P, [%0], %1, 0x989680;\n\t"
        "@P bra D%=;\n\t"
        "bra W%=;\n"
        "D%=:\n\t}"
        :: "r"(a), "r"(ph) : "memory");
}
__device__ __forceinline__ void bulk_g2s(uint32_t dst, const void* src, uint32_t bytes, uint32_t mbar) {
    asm volatile(
        "cp.async.bulk.shared::cluster.global.mbarrier::complete_tx::bytes [%0], [%1], %2, [%3];"
        :: "r"(dst), "l"(src), "r"(bytes), "r"(mbar) : "memory");
}
__device__ __forceinline__ void fence_async_shared() {
    asm volatile("fence.proxy.async.shared::cta;" ::: "memory");
}
__device__ __forceinline__ void ldsm4(uint32_t& r0, uint32_t& r1, uint32_t& r2, uint32_t& r3, uint32_t addr) {
    asm volatile("ldmatrix.sync.aligned.m8n8.x4.shared.b16 {%0,%1,%2,%3}, [%4];"
                 : "=r"(r0), "=r"(r1), "=r"(r2), "=r"(r3) : "r"(addr));
}
__device__ __forceinline__ void mma16816h(uint32_t* c, uint32_t a0, uint32_t a1, uint32_t a2, uint32_t a3,
                                          uint32_t b0, uint32_t b1) {
    asm volatile("mma.sync.aligned.m16n8k16.row.col.f16.f16.f16.f16 "
                 "{%0,%1}, {%2,%3,%4,%5}, {%6,%7}, {%0,%1};"
                 : "+r"(c[0]), "+r"(c[1])
                 : "r"(a0), "r"(a1), "r"(a2), "r"(a3), "r"(b0), "r"(b1));
}
__device__ __forceinline__ uint32_t sw128(uint32_t x) { return x ^ ((x >> 3) & 0x70); }

template<int L>
__device__ __forceinline__ void insL(float (&d)[L], int (&ix)[L], float v, int j) {
    if (v < d[L - 1]) {
        d[L - 1] = v; ix[L - 1] = j;
        #pragma unroll
        for (int p = L - 1; p > 0; p--) {
            if (d[p] < d[p - 1]) {
                float tf = d[p]; d[p] = d[p - 1]; d[p - 1] = tf;
                int   ti = ix[p]; ix[p] = ix[p - 1]; ix[p - 1] = ti;
            }
        }
    }
}

__device__ __forceinline__ void insS(float* fd, int* fidx, float& thr, float v, int j) {
    if (v < thr) {
        int p = LANEL - 1;
        #pragma unroll 1
        while (p > 0 && fd[p - 1] > v) {
            fd[p] = fd[p - 1]; fidx[p] = fidx[p - 1]; p--;
        }
        fd[p] = v; fidx[p] = j;
        thr = fd[LANEL - 1];
    }
}

// ---------------- kernel 0 ----------------
__global__ void zpsq_kernel(const float* __restrict__ protos, float4* out, int n4) {
    int i = blockIdx.x * blockDim.x + threadIdx.x;
    if (i < n4) out[i] = make_float4(0.f, 0.f, 0.f, 0.f);
    if (blockIdx.x == 0) {
        int tid = threadIdx.x;
        int w = tid >> 5, lane = tid & 31;
        for (int c = w; c < NCLS; c += 8) {
            float sacc = 0.f;
            for (int k = lane; k < CDIM; k += 32) {
                float v = protos[c * CDIM + k];
                sacc += v * v;
            }
            #pragma unroll
            for (int o = 16; o > 0; o >>= 1) sacc += __shfl_xor_sync(0xffffffffu, sacc, o);
            if (lane == 0) g_psq[c] = sacc;
        }
        if (tid < NT - NQ) g_fs[NQ + tid] = 1e30f;
    }
}

// ---------------- kernel 1 ----------------
__global__ void prep_kernel(const float* __restrict__ feat,
                            const float* __restrict__ outp,
                            const int* __restrict__ sidx) {
    const int i = blockIdx.x;
    const int tid = threadIdx.x;
    const int s = sidx[i];

    float acc = 0.f;
    float* dst = g_feats + (size_t)i * CDIM;
    for (int c = tid; c < CDIM; c += 128) {
        float v = __ldg(feat + (size_t)c * HWIN + s);
        dst[c] = v;
        acc += v * v;
    }
    __shared__ float red[128];
    __shared__ float sval[NCLS];
    red[tid] = acc;
    if (tid < NCLS) sval[tid] = __ldg(outp + (size_t)tid * HWIN + s);
    __syncthreads();
    for (int st = 64; st > 0; st >>= 1) {
        if (tid < st) red[tid] += red[tid + st];
        __syncthreads();
    }
    if (tid == 0) {
        g_fs[i] = red[0];
        float best = sval[0]; int bc = 0;
        #pragma unroll
        for (int c = 1; c < NCLS; c++)
            if (sval[c] > best) { best = sval[c]; bc = c; }
        g_cls[i] = bc;
    }
}

// ---------------- kernel 2 ----------------
__global__ void convert_kernel() {
    int idx = blockIdx.x * blockDim.x + threadIdx.x;
    if (idx >= NT * 64) return;
    int r  = idx >> 6;
    int g8 = idx & 63;
    int k  = g8 * 8;
    int c  = k >> 6;
    int kin = k & 63;

    uint4 u = make_uint4(0u, 0u, 0u, 0u);
    if (r < NQ) {
        const float4* src = (const float4*)(g_feats + (size_t)r * CDIM + k);
        float4 v0 = src[0], v1 = src[1];
        __half2 p0 = __float22half2_rn(make_float2(v0.x, v0.y));
        __half2 p1 = __float22half2_rn(make_float2(v0.z, v0.w));
        __half2 p2 = __float22half2_rn(make_float2(v1.x, v1.y));
        __half2 p3 = __float22half2_rn(make_float2(v1.z, v1.w));
        u.x = *(uint32_t*)&p0; u.y = *(uint32_t*)&p1;
        u.z = *(uint32_t*)&p2; u.w = *(uint32_t*)&p3;
    }
    size_t base = ((size_t)(r >> 7) * NCHUNK + c) * 16384 + (size_t)((r >> 3) & 15) * 1024;
    uint32_t inner = (uint32_t)((r & 7) * 128 + kin * 2);
    *(uint4*)((char*)g_featsh + base + sw128(inner)) = u;
}

// ---------------- kernel 3: M=128/CTA, A resident, A-prefetch, B-only stages ----
#define SM_A 1024
#define SM_B (1024 + 131072)                    // 132096
#define SM_LSTD (SM_B + NSTAGE * STAGEB)        // 181248
#define SM_LSTI (SM_LSTD + 512 * LANEL * 4)     // 205824
#define SM_TOTAL (SM_LSTI + 512 * LANEL * 4)    // 230400

__global__ __launch_bounds__(512, 1) void dist_select_kernel() {
    extern __shared__ char smem[];
    const uint32_t sb = smem_u32(smem);
    const uint32_t MB_FULL = sb + 0;
    const uint32_t MB_CONS = sb + 32;
    const uint32_t MB_A    = sb + 56;

    const int tid = threadIdx.x;
    const int w = tid >> 5, l = tid & 31;
    const int qg = l >> 2, t4 = l & 3;
    const int wr = w >> 1, wc = w & 1;     // 8x2 warp grid: 16 rows x 64 cols per warp
    const int blk = blockIdx.x;
    const int row0 = blk * 128;
    const unsigned FULL = 0xffffffffu;

    float* myd = (float*)(smem + SM_LSTD) + tid * LANEL;
    int*   myi = (int*)(smem + SM_LSTI) + tid * LANEL;
    #pragma unroll
    for (int k = 0; k < LANEL; k++) { myd[k] = 3.0e38f; myi[k] = 0; }
    float thr = 3.0e38f;

    if (tid == 0) {
        #pragma unroll
        for (int s = 0; s < NSTAGE; s++) {
            mbar_init(MB_FULL + 8 * s, 1);
            mbar_init(MB_CONS + 8 * s, 16);
        }
        mbar_init(MB_A, 1);
        fence_async_shared();
    }
    __syncthreads();

    if (tid == 0) {
        // A: this CTA's 128 rows, all 8 chunks, loaded ONCE
        mbar_expect(MB_A, 131072);
        #pragma unroll
        for (int c = 0; c < NCHUNK; c++)
            bulk_g2s(sb + SM_A + c * 16384,
                     (const char*)g_featsh + ((size_t)blk * NCHUNK + c) * 16384, 16384, MB_A);
        // B prologue: stages 0,1
        #pragma unroll
        for (int it0 = 0; it0 < 2; it0++) {
            mbar_expect(MB_FULL + 8 * it0, STAGEB);
            bulk_g2s(sb + SM_B + (uint32_t)it0 * STAGEB,
                     (const char*)g_featsh + (size_t)it0 * 16384, 16384, MB_FULL + 8 * it0);
        }
    }

    // ---- per-lane ldmatrix addressing (warp tile 16 rows x 64 cols) ----
    const int rowlA = l & 15;
    const int halfA = (l >> 4) & 1;
    const uint32_t maskA = (uint32_t)(rowlA & 7) << 4;
    const uint32_t aRowBase = (uint32_t)(wr * 16 + rowlA) * 128;
    const int rowlB = (l & 7) + ((l >> 4) << 3);
    const int halfB = (l >> 3) & 1;
    const uint32_t maskB = (uint32_t)(rowlB & 7) << 4;
    const uint32_t bRowBase = (uint32_t)(wc * 64 + rowlB) * 128;

    // epilogue row ownership: after one butterfly on t4 bit0,
    // lane (qg,t4) owns row wr*16 + qg + 8*(t4&1); lanes t4 and t4^2 share a row
    // and cover disjoint column pair-groups.
    uint32_t acc[8][2];
    #pragma unroll
    for (int n = 0; n < 8; n++) { acc[n][0] = 0u; acc[n][1] = 0u; }

    mbar_wait_acq(MB_A, 0);

    for (int it = 0; it < TOT; it++) {
        const int kc = it & 7;
        const int tile = it >> 3;

        if (tid == 0) {
            int il = it + 2;
            if (il < TOT) {
                int slot = il % NSTAGE;
                if (il >= NSTAGE)
                    mbar_wait_acq(MB_CONS + 8 * slot, (uint32_t)(((il - NSTAGE) / NSTAGE) & 1));
                int t2 = il >> 3, k2 = il & 7;
                mbar_expect(MB_FULL + 8 * slot, STAGEB);
                bulk_g2s(sb + SM_B + (uint32_t)slot * STAGEB,
                         (const char*)g_featsh + ((size_t)t2 * NCHUNK + k2) * 16384, 16384, MB_FULL + 8 * slot);
            }
        }

        // A fragment prefetch BEFORE B wait (A resident in smem)
        uint32_t af[4][4];
        const uint32_t abase = sb + SM_A + (uint32_t)kc * 16384 + aRowBase;
        #pragma unroll
        for (int ks = 0; ks < 4; ks++) {
            uint32_t acol = ((uint32_t)(ks * 32 + halfA * 16)) ^ maskA;
            ldsm4(af[ks][0], af[ks][1], af[ks][2], af[ks][3], abase + acol);
        }

        mbar_wait_acq(MB_FULL + 8 * (it % NSTAGE), (uint32_t)((it / NSTAGE) & 1));

        const uint32_t bbase = sb + SM_B + (uint32_t)(it % NSTAGE) * STAGEB + bRowBase;

        #pragma unroll
        for (int ks = 0; ks < 4; ks++) {
            uint32_t bcol = ((uint32_t)(ks * 32 + halfB * 16)) ^ maskB;
            #pragma unroll
            for (int p = 0; p < 4; p++) {
                uint32_t b0, b1, b2, b3;
                ldsm4(b0, b1, b2, b3, bbase + (uint32_t)p * 2048 + bcol);
                mma16816h(acc[2 * p],     af[ks][0], af[ks][1], af[ks][2], af[ks][3], b0, b1);
                mma16816h(acc[2 * p + 1], af[ks][0], af[ks][1], af[ks][2], af[ks][3], b2, b3);
            }
        }

        __syncwarp();
        if (l == 0) mbar_arrive(MB_CONS + 8 * (it % NSTAGE));

        if (kc == 7) {
            const int jb = tile * 128 + wc * 64;
            #pragma unroll
            for (int n8 = 0; n8 < 8; n8++) {
                uint32_t e0 = acc[n8][0], e1 = acc[n8][1];
                // butterfly on t4 bit0: each lane keeps the slot matching its bit0
                // (row qg + 8*(t4&1)) for BOTH its own cols and the partner's cols.
                uint32_t s0 = __shfl_xor_sync(FULL, e1, 1);   // partner's slot1
                uint32_t s1 = __shfl_xor_sync(FULL, e0, 1);   // partner's slot0
                bool lo = ((t4 & 1) == 0);
                // FIX (R14 bug): own-slot fragment always carries own cols 2*t4;
                // partner's same-slot fragment carries cols 2*(t4^1).
                uint32_t own = lo ? e0 : e1;                  // row = qg+8*(t4&1), cols 2*t4,2*t4+1
                uint32_t oth = lo ? s1 : s0;                  // same row, cols 2*(t4^1), +1
                float2 p0 = __half22float2(*(__half2*)&own);
                float2 p1 = __half22float2(*(__half2*)&oth);
                int c00 = n8 * 8 + 2 * t4;
                int c01 = n8 * 8 + 2 * (t4 ^ 1);
                insS(myd, myi, thr, fmaf(-2.f, p0.x, __ldg(g_fs + jb + c00)),     jb + c00);
                insS(myd, myi, thr, fmaf(-2.f, p0.y, __ldg(g_fs + jb + c00 + 1)), jb + c00 + 1);
                insS(myd, myi, thr, fmaf(-2.f, p1.x, __ldg(g_fs + jb + c01)),     jb + c01);
                insS(myd, myi, thr, fmaf(-2.f, p1.y, __ldg(g_fs + jb + c01 + 1)), jb + c01 + 1);
                acc[n8][0] = 0u; acc[n8][1] = 0u;
            }
        }
    }

    // ---- final merge: per row, 2 same-row lanes x 2 col-warps x 12 -> top-16 ----
    __syncthreads();
    if (tid < 128) {
        int row = row0 + tid;
        if (row < NQ) {
            int rwr = tid >> 4;          // row/16
            int rr  = tid & 15;
            int rqg = rr & 7;
            int rh  = (rr >> 3) & 1;     // row = qg + 8*rh -> lanes with t4&1 == rh
            float bd[SHORTL]; int bi[SHORTL];
            #pragma unroll
            for (int k = 0; k < SHORTL; k++) { bd[k] = 3.0e38f; bi[k] = 0; }
            #pragma unroll
            for (int wcc = 0; wcc < 2; wcc++) {
                #pragma unroll
                for (int tb = 0; tb < 2; tb++) {
                    int lt4 = rh + 2 * tb;
                    int lane = rqg * 4 + lt4;
                    int t = (rwr * 2 + wcc) * 32 + lane;
                    const float* dl = (const float*)(smem + SM_LSTD) + t * LANEL;
                    const int*   il = (const int*)(smem + SM_LSTI) + t * LANEL;
                    #pragma unroll
                    for (int e = 0; e < LANEL; e++) insL<SHORTL>(bd, bi, dl[e], il[e]);
                }
            }
            #pragma unroll
            for (int k = 0; k < SHORTL; k++) g_short[(size_t)row * SHORTL + k] = bi[k];
        }
    }
}

// ---------------- kernel 4: exact fp32 re-rank ----------------
__global__ __launch_bounds__(256) void rerank_kernel(const float* __restrict__ protos,
                                                     const int* __restrict__ sidx,
                                                     float* __restrict__ out) {
    const int q = blockIdx.x * 8 + (threadIdx.x >> 5);
    if (q >= NQ) return;
    const int lane = threadIdx.x & 31;
    const unsigned FULL = 0xffffffffu;

    float qv[16];
    const float* fr = g_feats + (size_t)q * CDIM;
    #pragma unroll
    for (int i = 0; i < 16; i++) qv[i] = fr[i * 32 + lane];
    const float fq = g_fs[q];

    int myidx = (lane < SHORTL) ? g_short[(size_t)q * SHORTL + lane] : 0x7fffffff;
    float myd = 1e38f;

    #pragma unroll 1
    for (int c = 0; c < SHORTL; c++) {
        int cj = __shfl_sync(FULL, myidx, c);
        const float* cr = g_feats + (size_t)cj * CDIM;
        float acc = 0.f;
        #pragma unroll
        for (int i = 0; i < 16; i++) acc += qv[i] * __ldg(&cr[i * 32 + lane]);
        #pragma unroll
        for (int o = 16; o > 0; o >>= 1) acc += __shfl_xor_sync(FULL, acc, o);
        float d = fmaxf(fq + __ldg(&g_fs[cj]) - 2.f * acc, 1e-12f);
        if (lane == c) myd = d;
    }

    int rank = 0;
    #pragma unroll
    for (int o = 0; o < SHORTL; o++) {
        float od = __shfl_sync(FULL, myd, o);
        int   oi = __shfl_sync(FULL, myidx, o);
        if (o != lane && (od < myd || (od == myd && oi < myidx))) rank++;
    }
    int nbcls = (lane < SHORTL && rank < KNN) ? g_cls[myidx] : -1;

    float ent = 0.f;
    #pragma unroll
    for (int c = 0; c < NCLS; c++) {
        int cnt = __popc(__ballot_sync(FULL, nbcls == c));
        if (cnt > 0) {
            float p = (float)cnt * (1.f / 9.f);
            ent += -p * logf(p + 1e-6f);
        }
    }
    ent *= (1.f / logf(19.f));

    float pd = 1e38f;
    #pragma unroll 1
    for (int c = 0; c < NCLS; c++) {
        float acc = 0.f;
        #pragma unroll
        for (int i = 0; i < 16; i++) acc += qv[i] * __ldg(&protos[c * CDIM + i * 32 + lane]);
        #pragma unroll
        for (int o = 16; o > 0; o >>= 1) acc += __shfl_xor_sync(FULL, acc, o);
        if (lane == c) pd = fmaxf(fq + g_psq[c] - 2.f * acc, 1e-12f);
    }
    int myc = g_cls[q];
    float refd = __shfl_sync(FULL, pd, myc);
    unsigned m = __ballot_sync(FULL, (lane < NCLS) && (pd < refd || (pd == refd && lane < myc)));
    int prank = __popc(m);

    if (lane == 0) {
        int s = sidx[q];
        out[s] = ent;
        out[FULLHW + s] = (float)prank * (1.f / 18.f);
    }
}

// ---------------- launch ----------------
extern "C" void kernel_launch(void* const* d_in, const int* in_sizes, int n_in,
                              void* d_out, int out_size) {
    const float* feat   = nullptr;
    const float* outp   = nullptr;
    const float* protos = nullptr;
    const int*   sidx   = nullptr;
    for (int i = 0; i < n_in; i++) {
        switch (in_sizes[i]) {
            case 66355200: feat   = (const float*)d_in[i]; break;
            case 2462400:  outp   = (const float*)d_in[i]; break;
            case 9728:     protos = (const float*)d_in[i]; break;
            case 32400:    sidx   = (const int*)d_in[i];   break;
        }
    }
    float* out = (float*)d_out;

    static bool attr_done = false;
    if (!attr_done) {
        cudaFuncSetAttribute(dist_select_kernel,
                             cudaFuncAttributeMaxDynamicSharedMemorySize, SM_TOTAL);
        attr_done = true;
    }

    int n4 = out_size / 4;
    zpsq_kernel<<<(n4 + 255) / 256, 256>>>(protos, (float4*)out, n4);
    prep_kernel<<<NQ, 128>>>(feat, outp, sidx);
    convert_kernel<<<(NT * 64 + 255) / 256, 256>>>();
    dist_select_kernel<<<NTILE, 512, SM_TOTAL>>>();
    rerank_kernel<<<(NQ + 7) / 8, 256>>>(protos, sidx, out);
}